// round 6
// baseline (speedup 1.0000x reference)
#include <cuda_runtime.h>

#define BB 32
#define NN 1024
#define FF 7
#define HID 256
#define MLPH 64
#define OUTD 8
#define THR2 0.09f
#define KCH 128         // K-chunks for MLP layer0
#define K4  14          // float4s per chunk (56 floats); 128*56 = 7168
#define SEGS 16         // kB segments per batch (64 rows each)

// ---- device scratch ----
__device__ unsigned g_adj[BB * NN * 32];        // adjacency bitmask, 4MB
__device__ float4   g_pack[BB * NN];            // (x, y, dinv, speed) per node
__device__ float    g_maxp[BB * 16];            // per-pair-block max dist^2 partials
__device__ float    g_upart[BB * SEGS * HID];   // per-seg partials of sum_j s_j h_j
__device__ float    g_speedp[BB * SEGS];        // per-seg speed sums
__device__ float    g_mpart[KCH * BB * MLPH];   // MLP layer0 K-chunk partials

// ============================================================================
// kA: blocks [0,512): pairwise adjacency. blocks [512,640): MLP0 chunk GEMM.
// ============================================================================
__global__ __launch_bounds__(256, 5) void kA(const float* __restrict__ x,
                                             const float* __restrict__ Wm0) {
    __shared__ float sbuf[K4 * MLPH * 4 + K4 * BB * 4 + 16];   // ~21.5KB
    int t = threadIdx.x;

    if (blockIdx.x < 512) {
        float2* s_pts = (float2*)sbuf;            // [NN] 8KB
        float*  s_max = sbuf + 2 * NN;            // [8]
        int b = blockIdx.x >> 4;
        int blk16 = blockIdx.x & 15;
        int rowbase = blk16 << 6;
        int lane = t & 31, w = t >> 5;

        for (int j = t; j < NN; j += 256) {
            const float* xr = x + ((size_t)b * NN + j) * FF;
            s_pts[j] = make_float2(xr[1], xr[2]);
        }
        __syncthreads();

        int i0 = rowbase + w * 8;
        float xi[8], yi[8]; unsigned word[8];
#pragma unroll
        for (int r = 0; r < 8; ++r) {
            float2 p = s_pts[i0 + r]; xi[r] = p.x; yi[r] = p.y; word[r] = 0u;
        }
        float mx = 0.f;
        for (int jw = 0; jw < 32; ++jw) {
            float2 pj = s_pts[jw * 32 + lane];
#pragma unroll
            for (int r = 0; r < 8; ++r) {
                float dx = xi[r] - pj.x, dy = yi[r] - pj.y;
                float d2 = fmaf(dx, dx, dy * dy);
                mx = fmaxf(mx, d2);
                unsigned m = __ballot_sync(0xffffffffu, d2 < THR2);
                if (lane == jw) word[r] = m;
            }
        }
#pragma unroll
        for (int r = 0; r < 8; ++r) {
            int i = i0 + r;
            g_adj[((size_t)b * NN + i) * 32 + lane] = word[r];
            int deg = __reduce_add_sync(0xffffffffu, __popc(word[r]));
            if (lane == 0) {
                const float* xr = x + ((size_t)b * NN + i) * FF;
                float s3 = xr[3], s4 = xr[4];
                g_pack[b * NN + i] = make_float4(
                    xi[r], yi[r], rsqrtf((float)deg),
                    sqrtf(fmaf(s3, s3, s4 * s4)));
            }
        }
        for (int o = 16; o > 0; o >>= 1)
            mx = fmaxf(mx, __shfl_xor_sync(0xffffffffu, mx, o));
        if (lane == 0) s_max[w] = mx;
        __syncthreads();
        if (t == 0) {
            float m = s_max[0];
#pragma unroll
            for (int k = 1; k < 8; ++k) m = fmaxf(m, s_max[k]);
            g_maxp[b * 16 + blk16] = m;
        }
    } else {
        int c = blockIdx.x - 512;
        float4* sw4 = (float4*)sbuf;                       // [K4][64]
        float4* sx4 = (float4*)(sbuf + K4 * MLPH * 4);     // [K4][32]
        const float4* W4 = (const float4*)Wm0;
        const float4* X4 = (const float4*)x;

        for (int i = t; i < MLPH * K4; i += 256) {
            int h = i / K4, k = i % K4;
            sw4[k * MLPH + h] = W4[(size_t)h * 1792 + c * K4 + k];
        }
        for (int i = t; i < BB * K4; i += 256) {
            int b = i / K4, k = i % K4;
            sx4[k * BB + b] = X4[(size_t)b * 1792 + c * K4 + k];
        }
        __syncthreads();

        if (t < 128) {
            int hb = t & 15;
            int bb = t >> 4;
            float acc[4][4] = {};
#pragma unroll
            for (int k = 0; k < K4; ++k) {
                float4 xv[4];
#pragma unroll
                for (int i = 0; i < 4; ++i) xv[i] = sx4[k * BB + bb + 8 * i];
#pragma unroll
                for (int j = 0; j < 4; ++j) {
                    float4 wv = sw4[k * MLPH + hb + 16 * j];
#pragma unroll
                    for (int i = 0; i < 4; ++i) {
                        acc[i][j] = fmaf(xv[i].x, wv.x, acc[i][j]);
                        acc[i][j] = fmaf(xv[i].y, wv.y, acc[i][j]);
                        acc[i][j] = fmaf(xv[i].z, wv.z, acc[i][j]);
                        acc[i][j] = fmaf(xv[i].w, wv.w, acc[i][j]);
                    }
                }
            }
#pragma unroll
            for (int i = 0; i < 4; ++i)
#pragma unroll
                for (int j = 0; j < 4; ++j)
                    g_mpart[((size_t)c * BB + bb + 8 * i) * MLPH + hb + 16 * j] = acc[i][j];
        }
    }
}

// ============================================================================
// kB: sparse graph pass, warp-per-row. Block = (batch, 64-row segment).
// lane l owns adjacency word l (coalesced 128B row load, ~0.7 set bits/lane),
// butterfly reduce. Then phase B: u-partials via W1+relu weighted row sum.
// ============================================================================
__global__ __launch_bounds__(256) void kB(const float* __restrict__ W1,
                                          const float* __restrict__ b1) {
    __shared__ float4 s_pack[NN];    // 16KB
    __shared__ float4 s_P[64];       // (Px, Py, S, -)
    __shared__ float  sred[64];
    int b = blockIdx.x >> 4, seg = blockIdx.x & 15;
    int row0 = seg * 64;
    int t = threadIdx.x, lane = t & 31, w = t >> 5;

    const float4* packb = g_pack + (size_t)b * NN;
    for (int j = t; j < NN; j += 256) s_pack[j] = packb[j];
    __syncthreads();

    // 8 rows per warp
#pragma unroll
    for (int rr = 0; rr < 8; ++rr) {
        int row = row0 + w * 8 + rr;
        unsigned m = g_adj[((size_t)b * NN + row) * 32 + lane];
        float wsum = 0.f, px = 0.f, py = 0.f;
        int base = lane * 32;
        while (m) {
            int j = base + __ffs(m) - 1;
            m &= m - 1;
            float4 p = s_pack[j];
            wsum += p.z;
            px = fmaf(p.z, p.x, px);
            py = fmaf(p.z, p.y, py);
        }
#pragma unroll
        for (int o = 16; o > 0; o >>= 1) {
            px   += __shfl_xor_sync(0xffffffffu, px, o);
            py   += __shfl_xor_sync(0xffffffffu, py, o);
            wsum += __shfl_xor_sync(0xffffffffu, wsum, o);
        }
        if (lane == 0) {
            float di = s_pack[row].z;
            s_P[w * 8 + rr] = make_float4(di * px, di * py, di * wsum, 0.f);
        }
    }
    if (t < 64) sred[t] = s_pack[row0 + t].w;
    __syncthreads();

    // speed partial: fixed-order tree reduce over 64
    for (int o = 32; o > 0; o >>= 1) {
        if (t < o) sred[t] += sred[t + o];
        __syncthreads();
    }
    if (t == 0) g_speedp[b * SEGS + seg] = sred[0];

    // phase B: thread k accumulates u_k over the 64 rows (fixed order)
    float w10 = W1[2 * t], w11 = W1[2 * t + 1], bk = b1[t];
    float acc = 0.f;
#pragma unroll 8
    for (int r = 0; r < 64; ++r) {
        float4 P = s_P[r];
        float h = fmaxf(fmaf(w10, P.x, fmaf(w11, P.y, bk)), 0.f);
        acc = fmaf(P.z, h, acc);
    }
    g_upart[((size_t)b * SEGS + seg) * HID + t] = acc;
}

// ============================================================================
// k3: per-batch finals.
// ============================================================================
__global__ void k3_final(const float* __restrict__ W2,  const float* __restrict__ b2,
                         const float* __restrict__ Wfc, const float* __restrict__ bfc,
                         const float* __restrict__ Wg,  const float* __restrict__ bg,
                         const float* __restrict__ Wm1, const float* __restrict__ bm1,
                         const float* __restrict__ bm0,
                         const float* __restrict__ Wp,  const float* __restrict__ bp,
                         float* __restrict__ out) {
    __shared__ float sm[HID], smid[HID], sgcn[HID], sglo[OUTD];
    __shared__ float sy0p[4][MLPH];
    __shared__ float sy0[MLPH], sy1[MLPH];
    int b = blockIdx.x, t = threadIdx.x;

    float u = 0.f;
#pragma unroll
    for (int c = 0; c < SEGS; ++c) u += g_upart[((size_t)b * SEGS + c) * HID + t];
    sm[t] = u * (1.0f / 1024.0f);

    // MLP chunk reduce across all 256 threads: 4 groups x 64 heads
    {
        int h = t & 63, grp = t >> 6;
        float a = 0.f;
#pragma unroll 8
        for (int k = 0; k < KCH / 4; ++k)
            a += g_mpart[((size_t)(grp * (KCH / 4) + k) * BB + b) * MLPH + h];
        sy0p[grp][h] = a;
    }
    __syncthreads();
    if (t < MLPH) {
        float a = sy0p[0][t] + sy0p[1][t] + sy0p[2][t] + sy0p[3][t];
        sy0[t] = fmaxf(a + bm0[t], 0.f);
    }
    __syncthreads();

    if (t < MLPH) {
        float a = bm1[t];
        const float* w = Wm1 + t * MLPH;
#pragma unroll 8
        for (int j = 0; j < MLPH; ++j) a = fmaf(w[j], sy0[j], a);
        sy1[t] = fmaxf(a, 0.f);
    }

    float a = b2[t];
    const float4* w2r = (const float4*)(W2 + (size_t)t * HID);
    const float4* smv = (const float4*)sm;
#pragma unroll 8
    for (int j = 0; j < HID / 4; ++j) {
        float4 wv = w2r[j], mv = smv[j];
        a = fmaf(wv.x, mv.x, a); a = fmaf(wv.y, mv.y, a);
        a = fmaf(wv.z, mv.z, a); a = fmaf(wv.w, mv.w, a);
    }
    smid[t] = a;
    __syncthreads();

    a = bfc[t];
    const float4* wfr  = (const float4*)(Wfc + (size_t)t * HID);
    const float4* smdv = (const float4*)smid;
#pragma unroll 8
    for (int j = 0; j < HID / 4; ++j) {
        float4 wv = wfr[j], mv = smdv[j];
        a = fmaf(wv.x, mv.x, a); a = fmaf(wv.y, mv.y, a);
        a = fmaf(wv.z, mv.z, a); a = fmaf(wv.w, mv.w, a);
    }
    sgcn[t] = a;

    if (t < OUTD) {
        float avg = 0.f;
#pragma unroll
        for (int c = 0; c < SEGS; ++c) avg += g_speedp[b * SEGS + c];
        avg *= (1.0f / 1024.0f);
        float mx = g_maxp[b * 16];
#pragma unroll
        for (int k = 1; k < 16; ++k) mx = fmaxf(mx, g_maxp[b * 16 + k]);
        float den = rsqrtf(mx);
        sglo[t] = fmaxf(fmaf(Wg[t * 2], avg, fmaf(Wg[t * 2 + 1], den, bg[t])), 0.f);
    }
    __syncthreads();

    if (t < OUTD) {
        float o = bp[t];
        const float* wp = Wp + t * (MLPH + HID + OUTD);
#pragma unroll 8
        for (int j = 0; j < MLPH; ++j) o = fmaf(wp[j], sy1[j], o);
#pragma unroll 8
        for (int j = 0; j < HID;  ++j) o = fmaf(wp[MLPH + j], sgcn[j], o);
#pragma unroll
        for (int j = 0; j < OUTD; ++j) o = fmaf(wp[MLPH + HID + j], sglo[j], o);
        out[b * OUTD + t] = o;
    }
}

extern "C" void kernel_launch(void* const* d_in, const int* in_sizes, int n_in,
                              void* d_out, int out_size) {
    const float* x   = (const float*)d_in[0];
    const float* W1  = (const float*)d_in[1];
    const float* b1  = (const float*)d_in[2];
    const float* W2  = (const float*)d_in[3];
    const float* b2  = (const float*)d_in[4];
    const float* Wfc = (const float*)d_in[5];
    const float* bfc = (const float*)d_in[6];
    const float* Wg  = (const float*)d_in[7];
    const float* bg  = (const float*)d_in[8];
    const float* Wm0 = (const float*)d_in[9];
    const float* bm0 = (const float*)d_in[10];
    const float* Wm1 = (const float*)d_in[11];
    const float* bm1 = (const float*)d_in[12];
    const float* Wp  = (const float*)d_in[13];
    const float* bp  = (const float*)d_in[14];
    float* out = (float*)d_out;

    kA<<<640, 256>>>(x, Wm0);
    kB<<<512, 256>>>(W1, b1);
    k3_final<<<32, 256>>>(W2, b2, Wfc, bfc, Wg, bg, Wm1, bm1, bm0, Wp, bp, out);
}

// round 7
// speedup vs baseline: 2.4887x; 2.4887x over previous
#include <cuda_runtime.h>

#define BB 32
#define NN 1024
#define FF 7
#define HID 256
#define MLPH 64
#define OUTD 8
#define THR2 0.09f
#define KCH 128         // K-chunks for MLP layer0
#define K4  14          // float4s per chunk (56 floats); 128*56 = 7168
#define SEGS 16         // kB segments per batch (64 rows each)
#define CAT (MLPH + HID + OUTD)   // 328

// ---- device scratch ----
__device__ unsigned g_adj[BB * NN * 32];        // adjacency bitmask, 4MB
__device__ float4   g_pack[BB * NN];            // (x, y, dinv, speed) per node
__device__ float    g_maxp[BB * 16];            // per-pair-block max dist^2 partials
__device__ float    g_upart[BB * SEGS * HID];   // per-seg partials of sum_j s_j h_j
__device__ float    g_speedp[BB * SEGS];        // per-seg speed sums
__device__ float    g_mpart[KCH * BB * MLPH];   // MLP layer0 K-chunk partials

// ============================================================================
// kA: blocks [0,512): pairwise adjacency. blocks [512,640): MLP0 chunk GEMM.
// ============================================================================
__global__ __launch_bounds__(256, 5) void kA(const float* __restrict__ x,
                                             const float* __restrict__ Wm0) {
    __shared__ float sbuf[K4 * MLPH * 4 + K4 * BB * 4 + 16];   // ~21.5KB
    int t = threadIdx.x;

    if (blockIdx.x < 512) {
        float2* s_pts = (float2*)sbuf;
        float*  s_max = sbuf + 2 * NN;
        int b = blockIdx.x >> 4;
        int blk16 = blockIdx.x & 15;
        int rowbase = blk16 << 6;
        int lane = t & 31, w = t >> 5;

        for (int j = t; j < NN; j += 256) {
            const float* xr = x + ((size_t)b * NN + j) * FF;
            s_pts[j] = make_float2(xr[1], xr[2]);
        }
        __syncthreads();

        int i0 = rowbase + w * 8;
        float xi[8], yi[8]; unsigned word[8];
#pragma unroll
        for (int r = 0; r < 8; ++r) {
            float2 p = s_pts[i0 + r]; xi[r] = p.x; yi[r] = p.y; word[r] = 0u;
        }
        float mx = 0.f;
        for (int jw = 0; jw < 32; ++jw) {
            float2 pj = s_pts[jw * 32 + lane];
#pragma unroll
            for (int r = 0; r < 8; ++r) {
                float dx = xi[r] - pj.x, dy = yi[r] - pj.y;
                float d2 = fmaf(dx, dx, dy * dy);
                mx = fmaxf(mx, d2);
                unsigned m = __ballot_sync(0xffffffffu, d2 < THR2);
                if (lane == jw) word[r] = m;
            }
        }
#pragma unroll
        for (int r = 0; r < 8; ++r) {
            int i = i0 + r;
            g_adj[((size_t)b * NN + i) * 32 + lane] = word[r];
            int deg = __reduce_add_sync(0xffffffffu, __popc(word[r]));
            if (lane == 0) {
                const float* xr = x + ((size_t)b * NN + i) * FF;
                float s3 = xr[3], s4 = xr[4];
                g_pack[b * NN + i] = make_float4(
                    xi[r], yi[r], rsqrtf((float)deg),
                    sqrtf(fmaf(s3, s3, s4 * s4)));
            }
        }
        for (int o = 16; o > 0; o >>= 1)
            mx = fmaxf(mx, __shfl_xor_sync(0xffffffffu, mx, o));
        if (lane == 0) s_max[w] = mx;
        __syncthreads();
        if (t == 0) {
            float m = s_max[0];
#pragma unroll
            for (int k = 1; k < 8; ++k) m = fmaxf(m, s_max[k]);
            g_maxp[b * 16 + blk16] = m;
        }
    } else {
        int c = blockIdx.x - 512;
        float4* sw4 = (float4*)sbuf;                       // [K4][64]
        float4* sx4 = (float4*)(sbuf + K4 * MLPH * 4);     // [K4][32]
        const float4* W4 = (const float4*)Wm0;
        const float4* X4 = (const float4*)x;

        for (int i = t; i < MLPH * K4; i += 256) {
            int h = i / K4, k = i % K4;
            sw4[k * MLPH + h] = W4[(size_t)h * 1792 + c * K4 + k];
        }
        for (int i = t; i < BB * K4; i += 256) {
            int b = i / K4, k = i % K4;
            sx4[k * BB + b] = X4[(size_t)b * 1792 + c * K4 + k];
        }
        __syncthreads();

        if (t < 128) {
            int hb = t & 15;
            int bb = t >> 4;
            float acc[4][4] = {};
#pragma unroll
            for (int k = 0; k < K4; ++k) {
                float4 xv[4];
#pragma unroll
                for (int i = 0; i < 4; ++i) xv[i] = sx4[k * BB + bb + 8 * i];
#pragma unroll
                for (int j = 0; j < 4; ++j) {
                    float4 wv = sw4[k * MLPH + hb + 16 * j];
#pragma unroll
                    for (int i = 0; i < 4; ++i) {
                        acc[i][j] = fmaf(xv[i].x, wv.x, acc[i][j]);
                        acc[i][j] = fmaf(xv[i].y, wv.y, acc[i][j]);
                        acc[i][j] = fmaf(xv[i].z, wv.z, acc[i][j]);
                        acc[i][j] = fmaf(xv[i].w, wv.w, acc[i][j]);
                    }
                }
            }
#pragma unroll
            for (int i = 0; i < 4; ++i)
#pragma unroll
                for (int j = 0; j < 4; ++j)
                    g_mpart[((size_t)c * BB + bb + 8 * i) * MLPH + hb + 16 * j] = acc[i][j];
        }
    }
}

// ============================================================================
// kB: sparse graph pass, warp-per-row. Block = (batch, 64-row segment).
// ============================================================================
__global__ __launch_bounds__(256) void kB(const float* __restrict__ W1,
                                          const float* __restrict__ b1) {
    __shared__ float4 s_pack[NN];    // 16KB
    __shared__ float4 s_P[64];
    __shared__ float  sred[64];
    int b = blockIdx.x >> 4, seg = blockIdx.x & 15;
    int row0 = seg * 64;
    int t = threadIdx.x, lane = t & 31, w = t >> 5;

    const float4* packb = g_pack + (size_t)b * NN;
    for (int j = t; j < NN; j += 256) s_pack[j] = packb[j];
    __syncthreads();

#pragma unroll
    for (int rr = 0; rr < 8; ++rr) {
        int row = row0 + w * 8 + rr;
        unsigned m = g_adj[((size_t)b * NN + row) * 32 + lane];
        float wsum = 0.f, px = 0.f, py = 0.f;
        int base = lane * 32;
        while (m) {
            int j = base + __ffs(m) - 1;
            m &= m - 1;
            float4 p = s_pack[j];
            wsum += p.z;
            px = fmaf(p.z, p.x, px);
            py = fmaf(p.z, p.y, py);
        }
#pragma unroll
        for (int o = 16; o > 0; o >>= 1) {
            px   += __shfl_xor_sync(0xffffffffu, px, o);
            py   += __shfl_xor_sync(0xffffffffu, py, o);
            wsum += __shfl_xor_sync(0xffffffffu, wsum, o);
        }
        if (lane == 0) {
            float di = s_pack[row].z;
            s_P[w * 8 + rr] = make_float4(di * px, di * py, di * wsum, 0.f);
        }
    }
    if (t < 64) sred[t] = s_pack[row0 + t].w;
    __syncthreads();

    for (int o = 32; o > 0; o >>= 1) {
        if (t < o) sred[t] += sred[t + o];
        __syncthreads();
    }
    if (t == 0) g_speedp[b * SEGS + seg] = sred[0];

    float w10 = W1[2 * t], w11 = W1[2 * t + 1], bk = b1[t];
    float acc = 0.f;
#pragma unroll 8
    for (int r = 0; r < 64; ++r) {
        float4 P = s_P[r];
        float h = fmaxf(fmaf(w10, P.x, fmaf(w11, P.y, bk)), 0.f);
        acc = fmaf(P.z, h, acc);
    }
    g_upart[((size_t)b * SEGS + seg) * HID + t] = acc;
}

// ============================================================================
// k3: per-batch finals — ALL matvecs warp-per-row, lane-strided (coalesced),
// butterfly shuffle reduce (fixed order => deterministic).
// ============================================================================
__global__ __launch_bounds__(256) void k3_final(
                         const float* __restrict__ W2,  const float* __restrict__ b2,
                         const float* __restrict__ Wfc, const float* __restrict__ bfc,
                         const float* __restrict__ Wg,  const float* __restrict__ bg,
                         const float* __restrict__ Wm1, const float* __restrict__ bm1,
                         const float* __restrict__ bm0,
                         const float* __restrict__ Wp,  const float* __restrict__ bp,
                         float* __restrict__ out) {
    __shared__ __align__(16) float sm[HID];
    __shared__ __align__(16) float smid[HID];
    __shared__ float sy0p[4][MLPH];
    __shared__ __align__(16) float sy0[MLPH];
    __shared__ __align__(16) float svec[CAT];   // [sy1(64) | sgcn(256) | sglo(8)]
    int b = blockIdx.x, t = threadIdx.x, lane = t & 31, w = t >> 5;

    // upart reduce -> sm (coalesced)
    float u = 0.f;
#pragma unroll
    for (int c = 0; c < SEGS; ++c) u += g_upart[((size_t)b * SEGS + c) * HID + t];
    sm[t] = u * (1.0f / 1024.0f);

    // mpart reduce (coalesced): 4 groups x 64 heads
    {
        int h = t & 63, grp = t >> 6;
        float a = 0.f;
#pragma unroll 8
        for (int k = 0; k < KCH / 4; ++k)
            a += g_mpart[((size_t)(grp * (KCH / 4) + k) * BB + b) * MLPH + h];
        sy0p[grp][h] = a;
    }
    __syncthreads();
    if (t < MLPH)
        sy0[t] = fmaxf(sy0p[0][t] + sy0p[1][t] + sy0p[2][t] + sy0p[3][t] + bm0[t], 0.f);
    __syncthreads();

    // Wm1: warp w -> rows w*8..w*8+7, lanes stride columns
#pragma unroll
    for (int k = 0; k < 8; ++k) {
        int r = w * 8 + k;
        float v = fmaf(Wm1[r * MLPH + lane], sy0[lane],
                       Wm1[r * MLPH + 32 + lane] * sy0[32 + lane]);
#pragma unroll
        for (int o = 16; o > 0; o >>= 1) v += __shfl_xor_sync(0xffffffffu, v, o);
        if (lane == 0) svec[r] = fmaxf(v + bm1[r], 0.f);
    }

    // W2 matvec: warp w -> rows w*32..w*32+31
    const float4* sm4 = (const float4*)sm;
    float4 m0 = sm4[lane], m1 = sm4[lane + 32];
#pragma unroll 4
    for (int k = 0; k < 32; ++k) {
        int r = w * 32 + k;
        const float4* wr = (const float4*)(W2 + (size_t)r * HID);
        float4 w0 = wr[lane], w1 = wr[lane + 32];
        float v = w0.x * m0.x + w0.y * m0.y + w0.z * m0.z + w0.w * m0.w
                + w1.x * m1.x + w1.y * m1.y + w1.z * m1.z + w1.w * m1.w;
#pragma unroll
        for (int o = 16; o > 0; o >>= 1) v += __shfl_xor_sync(0xffffffffu, v, o);
        if (lane == 0) smid[r] = v + b2[r];
    }
    __syncthreads();

    // Wfc matvec -> svec[64..320)
    const float4* sd4 = (const float4*)smid;
    float4 d0 = sd4[lane], d1 = sd4[lane + 32];
#pragma unroll 4
    for (int k = 0; k < 32; ++k) {
        int r = w * 32 + k;
        const float4* wr = (const float4*)(Wfc + (size_t)r * HID);
        float4 w0 = wr[lane], w1 = wr[lane + 32];
        float v = w0.x * d0.x + w0.y * d0.y + w0.z * d0.z + w0.w * d0.w
                + w1.x * d1.x + w1.y * d1.y + w1.z * d1.z + w1.w * d1.w;
#pragma unroll
        for (int o = 16; o > 0; o >>= 1) v += __shfl_xor_sync(0xffffffffu, v, o);
        if (lane == 0) svec[MLPH + r] = v + bfc[r];
    }

    // global branch -> svec[320..328)
    if (t < OUTD) {
        float avg = 0.f;
#pragma unroll
        for (int c = 0; c < SEGS; ++c) avg += g_speedp[b * SEGS + c];
        avg *= (1.0f / 1024.0f);
        float mx = g_maxp[b * 16];
#pragma unroll
        for (int k = 1; k < 16; ++k) mx = fmaxf(mx, g_maxp[b * 16 + k]);
        float den = rsqrtf(mx);
        svec[MLPH + HID + t] =
            fmaxf(fmaf(Wg[t * 2], avg, fmaf(Wg[t * 2 + 1], den, bg[t])), 0.f);
    }
    __syncthreads();

    // Wp: warp w computes output w (w < 8), lanes stride the 328 inputs
    if (w < OUTD) {
        const float* wp = Wp + (size_t)w * CAT;
        float o = 0.f;
#pragma unroll
        for (int j = lane; j < CAT; j += 32) o = fmaf(wp[j], svec[j], o);
#pragma unroll
        for (int s = 16; s > 0; s >>= 1) o += __shfl_xor_sync(0xffffffffu, o, s);
        if (lane == 0) out[b * OUTD + w] = o + bp[w];
    }
}

extern "C" void kernel_launch(void* const* d_in, const int* in_sizes, int n_in,
                              void* d_out, int out_size) {
    const float* x   = (const float*)d_in[0];
    const float* W1  = (const float*)d_in[1];
    const float* b1  = (const float*)d_in[2];
    const float* W2  = (const float*)d_in[3];
    const float* b2  = (const float*)d_in[4];
    const float* Wfc = (const float*)d_in[5];
    const float* bfc = (const float*)d_in[6];
    const float* Wg  = (const float*)d_in[7];
    const float* bg  = (const float*)d_in[8];
    const float* Wm0 = (const float*)d_in[9];
    const float* bm0 = (const float*)d_in[10];
    const float* Wm1 = (const float*)d_in[11];
    const float* bm1 = (const float*)d_in[12];
    const float* Wp  = (const float*)d_in[13];
    const float* bp  = (const float*)d_in[14];
    float* out = (float*)d_out;

    kA<<<640, 256>>>(x, Wm0);
    kB<<<512, 256>>>(W1, b1);
    k3_final<<<32, 256>>>(W2, b2, Wfc, bfc, Wg, bg, Wm1, bm1, bm0, Wp, bp, out);
}

// round 8
// speedup vs baseline: 2.5088x; 1.0081x over previous
#include <cuda_runtime.h>

#define BB 32
#define NN 1024
#define FF 7
#define HID 256
#define MLPH 64
#define OUTD 8
#define THR2 0.09f
#define KCH 128         // K-chunks for MLP layer0
#define K4  14          // float4s per chunk (56 floats); 128*56 = 7168
#define SEGS 16         // kB segments per batch (64 rows each)
#define CAT (MLPH + HID + OUTD)   // 328
#define PBLK 1024       // pair blocks (32 per batch, 32 rows each)

// ---- device scratch ----
__device__ unsigned g_adj[BB * NN * 32];        // adjacency bitmask, 4MB
__device__ float4   g_pack[BB * NN];            // (x, y, dinv, speed) per node
__device__ float    g_maxp[BB * 32];            // per-pair-block max dist^2 partials
__device__ float    g_upart[BB * SEGS * HID];   // per-seg partials of sum_j s_j h_j
__device__ float    g_speedp[BB * SEGS];        // per-seg speed sums
__device__ float    g_mpart[KCH * BB * MLPH];   // MLP layer0 K-chunk partials

// ============================================================================
// kA: blocks [0,1024): pairwise adjacency (32 rows each).
//     blocks [1024,1152): MLP0 chunk GEMM (all 256 threads, 2x4 tile).
// ============================================================================
__global__ __launch_bounds__(256, 6) void kA(const float* __restrict__ x,
                                             const float* __restrict__ Wm0) {
    __shared__ float sbuf[K4 * MLPH * 4 + K4 * BB * 4 + 16];   // ~21.5KB
    int t = threadIdx.x;

    if (blockIdx.x < PBLK) {
        float2* s_pts = (float2*)sbuf;
        float*  s_max = sbuf + 2 * NN;
        int b = blockIdx.x >> 5;
        int blk32 = blockIdx.x & 31;
        int rowbase = blk32 << 5;                 // 32 rows per block
        int lane = t & 31, w = t >> 5;

        for (int j = t; j < NN; j += 256) {
            const float* xr = x + ((size_t)b * NN + j) * FF;
            s_pts[j] = make_float2(xr[1], xr[2]);
        }
        __syncthreads();

        int i0 = rowbase + w * 4;
        float xi[4], yi[4]; unsigned word[4];
#pragma unroll
        for (int r = 0; r < 4; ++r) {
            float2 p = s_pts[i0 + r]; xi[r] = p.x; yi[r] = p.y; word[r] = 0u;
        }
        float mx = 0.f;
        for (int jw = 0; jw < 32; ++jw) {
            float2 pj = s_pts[jw * 32 + lane];
#pragma unroll
            for (int r = 0; r < 4; ++r) {
                float dx = xi[r] - pj.x, dy = yi[r] - pj.y;
                float d2 = fmaf(dx, dx, dy * dy);
                mx = fmaxf(mx, d2);
                unsigned m = __ballot_sync(0xffffffffu, d2 < THR2);
                if (lane == jw) word[r] = m;
            }
        }
#pragma unroll
        for (int r = 0; r < 4; ++r) {
            int i = i0 + r;
            g_adj[((size_t)b * NN + i) * 32 + lane] = word[r];
            int deg = __reduce_add_sync(0xffffffffu, __popc(word[r]));
            if (lane == 0) {
                const float* xr = x + ((size_t)b * NN + i) * FF;
                float s3 = xr[3], s4 = xr[4];
                g_pack[b * NN + i] = make_float4(
                    xi[r], yi[r], rsqrtf((float)deg),
                    sqrtf(fmaf(s3, s3, s4 * s4)));
            }
        }
        for (int o = 16; o > 0; o >>= 1)
            mx = fmaxf(mx, __shfl_xor_sync(0xffffffffu, mx, o));
        if (lane == 0) s_max[w] = mx;
        __syncthreads();
        if (t == 0) {
            float m = s_max[0];
#pragma unroll
            for (int k = 1; k < 8; ++k) m = fmaxf(m, s_max[k]);
            g_maxp[b * 32 + blk32] = m;
        }
    } else {
        int c = blockIdx.x - PBLK;
        float4* sw4 = (float4*)sbuf;                       // [K4][64]
        float4* sx4 = (float4*)(sbuf + K4 * MLPH * 4);     // [K4][32]
        const float4* W4 = (const float4*)Wm0;
        const float4* X4 = (const float4*)x;

        for (int i = t; i < MLPH * K4; i += 256) {
            int h = i / K4, k = i % K4;
            sw4[k * MLPH + h] = W4[(size_t)h * 1792 + c * K4 + k];
        }
        for (int i = t; i < BB * K4; i += 256) {
            int b = i / K4, k = i % K4;
            sx4[k * BB + b] = X4[(size_t)b * 1792 + c * K4 + k];
        }
        __syncthreads();

        // 256 threads, each 2 batches x 4 heads
        int hb = t & 15;        // heads hb + 16j, j<4
        int bbase = t >> 4;     // 0..15, batches bbase + 16i, i<2
        float acc[2][4] = {};
#pragma unroll
        for (int k = 0; k < K4; ++k) {
            float4 xv[2];
#pragma unroll
            for (int i = 0; i < 2; ++i) xv[i] = sx4[k * BB + bbase + 16 * i];
#pragma unroll
            for (int j = 0; j < 4; ++j) {
                float4 wv = sw4[k * MLPH + hb + 16 * j];
#pragma unroll
                for (int i = 0; i < 2; ++i) {
                    acc[i][j] = fmaf(xv[i].x, wv.x, acc[i][j]);
                    acc[i][j] = fmaf(xv[i].y, wv.y, acc[i][j]);
                    acc[i][j] = fmaf(xv[i].z, wv.z, acc[i][j]);
                    acc[i][j] = fmaf(xv[i].w, wv.w, acc[i][j]);
                }
            }
        }
#pragma unroll
        for (int i = 0; i < 2; ++i)
#pragma unroll
            for (int j = 0; j < 4; ++j)
                g_mpart[((size_t)c * BB + bbase + 16 * i) * MLPH + hb + 16 * j] = acc[i][j];
    }
}

// ============================================================================
// kB: sparse graph pass, warp-per-row. Block = (batch, 64-row segment).
// ============================================================================
__global__ __launch_bounds__(256) void kB(const float* __restrict__ W1,
                                          const float* __restrict__ b1) {
    __shared__ float4 s_pack[NN];    // 16KB
    __shared__ float4 s_P[64];
    __shared__ float  sred[64];
    int b = blockIdx.x >> 4, seg = blockIdx.x & 15;
    int row0 = seg * 64;
    int t = threadIdx.x, lane = t & 31, w = t >> 5;

    const float4* packb = g_pack + (size_t)b * NN;
    for (int j = t; j < NN; j += 256) s_pack[j] = packb[j];
    __syncthreads();

#pragma unroll
    for (int rr = 0; rr < 8; ++rr) {
        int row = row0 + w * 8 + rr;
        unsigned m = g_adj[((size_t)b * NN + row) * 32 + lane];
        float wsum = 0.f, px = 0.f, py = 0.f;
        int base = lane * 32;
        while (m) {
            int j = base + __ffs(m) - 1;
            m &= m - 1;
            float4 p = s_pack[j];
            wsum += p.z;
            px = fmaf(p.z, p.x, px);
            py = fmaf(p.z, p.y, py);
        }
#pragma unroll
        for (int o = 16; o > 0; o >>= 1) {
            px   += __shfl_xor_sync(0xffffffffu, px, o);
            py   += __shfl_xor_sync(0xffffffffu, py, o);
            wsum += __shfl_xor_sync(0xffffffffu, wsum, o);
        }
        if (lane == 0) {
            float di = s_pack[row].z;
            s_P[w * 8 + rr] = make_float4(di * px, di * py, di * wsum, 0.f);
        }
    }
    if (t < 64) sred[t] = s_pack[row0 + t].w;
    __syncthreads();

    for (int o = 32; o > 0; o >>= 1) {
        if (t < o) sred[t] += sred[t + o];
        __syncthreads();
    }
    if (t == 0) g_speedp[b * SEGS + seg] = sred[0];

    float w10 = W1[2 * t], w11 = W1[2 * t + 1], bk = b1[t];
    float acc = 0.f;
#pragma unroll 8
    for (int r = 0; r < 64; ++r) {
        float4 P = s_P[r];
        float h = fmaxf(fmaf(w10, P.x, fmaf(w11, P.y, bk)), 0.f);
        acc = fmaf(P.z, h, acc);
    }
    g_upart[((size_t)b * SEGS + seg) * HID + t] = acc;
}

// ============================================================================
// k3: per-batch finals — all matvecs warp-per-row, coalesced, shuffle reduce.
// ============================================================================
__global__ __launch_bounds__(256) void k3_final(
                         const float* __restrict__ W2,  const float* __restrict__ b2,
                         const float* __restrict__ Wfc, const float* __restrict__ bfc,
                         const float* __restrict__ Wg,  const float* __restrict__ bg,
                         const float* __restrict__ Wm1, const float* __restrict__ bm1,
                         const float* __restrict__ bm0,
                         const float* __restrict__ Wp,  const float* __restrict__ bp,
                         float* __restrict__ out) {
    __shared__ __align__(16) float sm[HID];
    __shared__ __align__(16) float smid[HID];
    __shared__ float sy0p[4][MLPH];
    __shared__ __align__(16) float sy0[MLPH];
    __shared__ __align__(16) float svec[CAT];   // [sy1(64) | sgcn(256) | sglo(8)]
    int b = blockIdx.x, t = threadIdx.x, lane = t & 31, w = t >> 5;

    float u = 0.f;
#pragma unroll
    for (int c = 0; c < SEGS; ++c) u += g_upart[((size_t)b * SEGS + c) * HID + t];
    sm[t] = u * (1.0f / 1024.0f);

    {
        int h = t & 63, grp = t >> 6;
        float a = 0.f;
#pragma unroll 8
        for (int k = 0; k < KCH / 4; ++k)
            a += g_mpart[((size_t)(grp * (KCH / 4) + k) * BB + b) * MLPH + h];
        sy0p[grp][h] = a;
    }
    __syncthreads();
    if (t < MLPH)
        sy0[t] = fmaxf(sy0p[0][t] + sy0p[1][t] + sy0p[2][t] + sy0p[3][t] + bm0[t], 0.f);
    __syncthreads();

#pragma unroll
    for (int k = 0; k < 8; ++k) {
        int r = w * 8 + k;
        float v = fmaf(Wm1[r * MLPH + lane], sy0[lane],
                       Wm1[r * MLPH + 32 + lane] * sy0[32 + lane]);
#pragma unroll
        for (int o = 16; o > 0; o >>= 1) v += __shfl_xor_sync(0xffffffffu, v, o);
        if (lane == 0) svec[r] = fmaxf(v + bm1[r], 0.f);
    }

    const float4* sm4 = (const float4*)sm;
    float4 m0 = sm4[lane], m1 = sm4[lane + 32];
#pragma unroll 4
    for (int k = 0; k < 32; ++k) {
        int r = w * 32 + k;
        const float4* wr = (const float4*)(W2 + (size_t)r * HID);
        float4 w0 = wr[lane], w1 = wr[lane + 32];
        float v = w0.x * m0.x + w0.y * m0.y + w0.z * m0.z + w0.w * m0.w
                + w1.x * m1.x + w1.y * m1.y + w1.z * m1.z + w1.w * m1.w;
#pragma unroll
        for (int o = 16; o > 0; o >>= 1) v += __shfl_xor_sync(0xffffffffu, v, o);
        if (lane == 0) smid[r] = v + b2[r];
    }
    __syncthreads();

    const float4* sd4 = (const float4*)smid;
    float4 d0 = sd4[lane], d1 = sd4[lane + 32];
#pragma unroll 4
    for (int k = 0; k < 32; ++k) {
        int r = w * 32 + k;
        const float4* wr = (const float4*)(Wfc + (size_t)r * HID);
        float4 w0 = wr[lane], w1 = wr[lane + 32];
        float v = w0.x * d0.x + w0.y * d0.y + w0.z * d0.z + w0.w * d0.w
                + w1.x * d1.x + w1.y * d1.y + w1.z * d1.z + w1.w * d1.w;
#pragma unroll
        for (int o = 16; o > 0; o >>= 1) v += __shfl_xor_sync(0xffffffffu, v, o);
        if (lane == 0) svec[MLPH + r] = v + bfc[r];
    }

    if (t < OUTD) {
        float avg = 0.f;
#pragma unroll
        for (int c = 0; c < SEGS; ++c) avg += g_speedp[b * SEGS + c];
        avg *= (1.0f / 1024.0f);
        float mx = g_maxp[b * 32];
#pragma unroll
        for (int k = 1; k < 32; ++k) mx = fmaxf(mx, g_maxp[b * 32 + k]);
        float den = rsqrtf(mx);
        svec[MLPH + HID + t] =
            fmaxf(fmaf(Wg[t * 2], avg, fmaf(Wg[t * 2 + 1], den, bg[t])), 0.f);
    }
    __syncthreads();

    if (w < OUTD) {
        const float* wp = Wp + (size_t)w * CAT;
        float o = 0.f;
#pragma unroll
        for (int j = lane; j < CAT; j += 32) o = fmaf(wp[j], svec[j], o);
#pragma unroll
        for (int s = 16; s > 0; s >>= 1) o += __shfl_xor_sync(0xffffffffu, o, s);
        if (lane == 0) out[b * OUTD + w] = o + bp[w];
    }
}

extern "C" void kernel_launch(void* const* d_in, const int* in_sizes, int n_in,
                              void* d_out, int out_size) {
    const float* x   = (const float*)d_in[0];
    const float* W1  = (const float*)d_in[1];
    const float* b1  = (const float*)d_in[2];
    const float* W2  = (const float*)d_in[3];
    const float* b2  = (const float*)d_in[4];
    const float* Wfc = (const float*)d_in[5];
    const float* bfc = (const float*)d_in[6];
    const float* Wg  = (const float*)d_in[7];
    const float* bg  = (const float*)d_in[8];
    const float* Wm0 = (const float*)d_in[9];
    const float* bm0 = (const float*)d_in[10];
    const float* Wm1 = (const float*)d_in[11];
    const float* bm1 = (const float*)d_in[12];
    const float* Wp  = (const float*)d_in[13];
    const float* bp  = (const float*)d_in[14];
    float* out = (float*)d_out;

    kA<<<PBLK + KCH, 256>>>(x, Wm0);
    kB<<<512, 256>>>(W1, b1);
    k3_final<<<32, 256>>>(W2, b2, Wfc, bfc, Wg, bg, Wm1, bm1, bm0, Wp, bp, out);
}

// round 12
// speedup vs baseline: 2.6309x; 1.0486x over previous
#include <cuda_runtime.h>

#define BB 32
#define NN 1024
#define FF 7
#define HID 256
#define MLPH 64
#define OUTD 8
#define THR2 0.09f
#define KCH 128         // K-chunks for MLP layer0
#define K4  14          // float4s per chunk (56 floats); 128*56 = 7168
#define SEGS 16         // kB segments per batch (64 rows each)
#define CAT (MLPH + HID + OUTD)   // 328
#define PBLK 128        // pair blocks: 4 per batch, 256 rows each

// ---- device scratch ----
__device__ unsigned g_adj[BB * NN * 32];        // adjacency bitmask, 4MB
__device__ float4   g_pack[BB * NN];            // (x, y, dinv, speed) per node
__device__ float    g_maxp[BB * 4];             // per-pair-block max dist^2 partials
__device__ float    g_upart[BB * SEGS * HID];   // per-seg partials of sum_j s_j h_j
__device__ float    g_speedp[BB * SEGS];        // per-seg speed sums
__device__ float    g_mpart[KCH * BB * MLPH];   // MLP layer0 K-chunk partials

// smem: pairs path needs 2048 (pts) + 256*33 (words) + 8 (max) = 10504 floats ~42KB
#define SBUF_F (2048 + 256 * 33 + 8)

// ============================================================================
// kA: blocks [0,128): pairwise adjacency, lane-per-row, NO ballot.
//     blocks [128,256): MLP0 chunk GEMM (all 256 threads, 2x4 tile).
// ============================================================================
__global__ __launch_bounds__(256, 5) void kA(const float* __restrict__ x,
                                             const float* __restrict__ Wm0) {
    __shared__ float sbuf[SBUF_F];
    int t = threadIdx.x;

    if (blockIdx.x < PBLK) {
        float2*   s_pts   = (float2*)sbuf;                    // [1024]
        unsigned* s_words = (unsigned*)(sbuf + 2048);         // [256][33] padded
        float*    s_max   = sbuf + 2048 + 256 * 33;           // [8]
        int b = blockIdx.x >> 2, q = blockIdx.x & 3;
        int rowbase = q << 8;
        int lane = t & 31, w = t >> 5;

        for (int j = t; j < NN; j += 256) {
            const float* xr = x + ((size_t)b * NN + j) * FF;
            s_pts[j] = make_float2(xr[1], xr[2]);
        }
        __syncthreads();

        int lrow = w * 32 + lane;          // 0..255 (local row)
        int row  = rowbase + lrow;
        float xi = s_pts[row].x, yi = s_pts[row].y;
        float mx = 0.f;
        int deg = 0;
        unsigned* swr = s_words + lrow * 33;

        for (int jw = 0; jw < 32; ++jw) {
            const float4* p4 = (const float4*)(s_pts + jw * 32);
            unsigned word = 0;
#pragma unroll
            for (int k = 0; k < 16; ++k) {
                float4 pp = p4[k];                    // 2 points, warp-broadcast
                float dx = xi - pp.x, dy = yi - pp.y;
                float d2 = fmaf(dx, dx, dy * dy);
                mx = fmaxf(mx, d2);
                if (d2 < THR2) word |= (1u << (2 * k));
                dx = xi - pp.z; dy = yi - pp.w;
                d2 = fmaf(dx, dx, dy * dy);
                mx = fmaxf(mx, d2);
                if (d2 < THR2) word |= (1u << (2 * k + 1));
            }
            swr[jw] = word;
            deg += __popc(word);
        }

        // pack write: lanes = consecutive rows -> coalesced STG.128
        {
            const float* xr = x + ((size_t)b * NN + row) * FF;
            float s3 = xr[3], s4 = xr[4];
            g_pack[b * NN + row] = make_float4(
                xi, yi, rsqrtf((float)deg), sqrtf(fmaf(s3, s3, s4 * s4)));
        }

        // max reduce
        for (int o = 16; o > 0; o >>= 1)
            mx = fmaxf(mx, __shfl_xor_sync(0xffffffffu, mx, o));
        if (lane == 0) s_max[w] = mx;
        __syncthreads();
        if (t == 0) {
            float m = s_max[0];
#pragma unroll
            for (int k = 1; k < 8; ++k) m = fmaxf(m, s_max[k]);
            g_maxp[b * 4 + q] = m;
        }

        // coalesced copy of adjacency words
        unsigned* dst = g_adj + ((size_t)b * NN + rowbase) * 32;
        for (int idx = t; idx < 256 * 32; idx += 256) {
            int r = idx >> 5, wi = idx & 31;
            dst[idx] = s_words[r * 33 + wi];
        }
    } else {
        int c = blockIdx.x - PBLK;
        float4* sw4 = (float4*)sbuf;                       // [K4][64]
        float4* sx4 = (float4*)(sbuf + K4 * MLPH * 4);     // [K4][32]
        const float4* W4 = (const float4*)Wm0;
        const float4* X4 = (const float4*)x;

        for (int i = t; i < MLPH * K4; i += 256) {
            int h = i / K4, k = i % K4;
            sw4[k * MLPH + h] = W4[(size_t)h * 1792 + c * K4 + k];
        }
        for (int i = t; i < BB * K4; i += 256) {
            int b = i / K4, k = i % K4;
            sx4[k * BB + b] = X4[(size_t)b * 1792 + c * K4 + k];
        }
        __syncthreads();

        int hb = t & 15;        // heads hb + 16j, j<4
        int bbase = t >> 4;     // batches bbase + 16i, i<2
        float acc[2][4] = {};
#pragma unroll
        for (int k = 0; k < K4; ++k) {
            float4 xv[2];
#pragma unroll
            for (int i = 0; i < 2; ++i) xv[i] = sx4[k * BB + bbase + 16 * i];
#pragma unroll
            for (int j = 0; j < 4; ++j) {
                float4 wv = sw4[k * MLPH + hb + 16 * j];
#pragma unroll
                for (int i = 0; i < 2; ++i) {
                    acc[i][j] = fmaf(xv[i].x, wv.x, acc[i][j]);
                    acc[i][j] = fmaf(xv[i].y, wv.y, acc[i][j]);
                    acc[i][j] = fmaf(xv[i].z, wv.z, acc[i][j]);
                    acc[i][j] = fmaf(xv[i].w, wv.w, acc[i][j]);
                }
            }
        }
#pragma unroll
        for (int i = 0; i < 2; ++i)
#pragma unroll
            for (int j = 0; j < 4; ++j)
                g_mpart[((size_t)c * BB + bbase + 16 * i) * MLPH + hb + 16 * j] = acc[i][j];
    }
}

// ============================================================================
// kB: sparse graph pass, warp-per-row. Block = (batch, 64-row segment).
// ============================================================================
__global__ __launch_bounds__(256) void kB(const float* __restrict__ W1,
                                          const float* __restrict__ b1) {
    __shared__ float4 s_pack[NN];    // 16KB
    __shared__ float4 s_P[64];
    __shared__ float  sred[64];
    int b = blockIdx.x >> 4, seg = blockIdx.x & 15;
    int row0 = seg * 64;
    int t = threadIdx.x, lane = t & 31, w = t >> 5;

    const float4* packb = g_pack + (size_t)b * NN;
    for (int j = t; j < NN; j += 256) s_pack[j] = packb[j];
    __syncthreads();

#pragma unroll
    for (int rr = 0; rr < 8; ++rr) {
        int row = row0 + w * 8 + rr;
        unsigned m = g_adj[((size_t)b * NN + row) * 32 + lane];
        float wsum = 0.f, px = 0.f, py = 0.f;
        int base = lane * 32;
        while (m) {
            int j = base + __ffs(m) - 1;
            m &= m - 1;
            float4 p = s_pack[j];
            wsum += p.z;
            px = fmaf(p.z, p.x, px);
            py = fmaf(p.z, p.y, py);
        }
#pragma unroll
        for (int o = 16; o > 0; o >>= 1) {
            px   += __shfl_xor_sync(0xffffffffu, px, o);
            py   += __shfl_xor_sync(0xffffffffu, py, o);
            wsum += __shfl_xor_sync(0xffffffffu, wsum, o);
        }
        if (lane == 0) {
            float di = s_pack[row].z;
            s_P[w * 8 + rr] = make_float4(di * px, di * py, di * wsum, 0.f);
        }
    }
    if (t < 64) sred[t] = s_pack[row0 + t].w;
    __syncthreads();

    for (int o = 32; o > 0; o >>= 1) {
        if (t < o) sred[t] += sred[t + o];
        __syncthreads();
    }
    if (t == 0) g_speedp[b * SEGS + seg] = sred[0];

    float w10 = W1[2 * t], w11 = W1[2 * t + 1], bk = b1[t];
    float acc = 0.f;
#pragma unroll 8
    for (int r = 0; r < 64; ++r) {
        float4 P = s_P[r];
        float h = fmaxf(fmaf(w10, P.x, fmaf(w11, P.y, bk)), 0.f);
        acc = fmaf(P.z, h, acc);
    }
    g_upart[((size_t)b * SEGS + seg) * HID + t] = acc;
}

// ============================================================================
// k3: per-batch finals — all matvecs warp-per-row, coalesced, shuffle reduce.
// ============================================================================
__global__ __launch_bounds__(256) void k3_final(
                         const float* __restrict__ W2,  const float* __restrict__ b2,
                         const float* __restrict__ Wfc, const float* __restrict__ bfc,
                         const float* __restrict__ Wg,  const float* __restrict__ bg,
                         const float* __restrict__ Wm1, const float* __restrict__ bm1,
                         const float* __restrict__ bm0,
                         const float* __restrict__ Wp,  const float* __restrict__ bp,
                         float* __restrict__ out) {
    __shared__ __align__(16) float sm[HID];
    __shared__ __align__(16) float smid[HID];
    __shared__ float sy0p[4][MLPH];
    __shared__ __align__(16) float sy0[MLPH];
    __shared__ __align__(16) float svec[CAT];   // [sy1(64) | sgcn(256) | sglo(8)]
    int b = blockIdx.x, t = threadIdx.x, lane = t & 31, w = t >> 5;

    float u = 0.f;
#pragma unroll
    for (int c = 0; c < SEGS; ++c) u += g_upart[((size_t)b * SEGS + c) * HID + t];
    sm[t] = u * (1.0f / 1024.0f);

    {
        int h = t & 63, grp = t >> 6;
        float a = 0.f;
#pragma unroll 8
        for (int k = 0; k < KCH / 4; ++k)
            a += g_mpart[((size_t)(grp * (KCH / 4) + k) * BB + b) * MLPH + h];
        sy0p[grp][h] = a;
    }
    __syncthreads();
    if (t < MLPH)
        sy0[t] = fmaxf(sy0p[0][t] + sy0p[1][t] + sy0p[2][t] + sy0p[3][t] + bm0[t], 0.f);
    __syncthreads();

#pragma unroll
    for (int k = 0; k < 8; ++k) {
        int r = w * 8 + k;
        float v = fmaf(Wm1[r * MLPH + lane], sy0[lane],
                       Wm1[r * MLPH + 32 + lane] * sy0[32 + lane]);
#pragma unroll
        for (int o = 16; o > 0; o >>= 1) v += __shfl_xor_sync(0xffffffffu, v, o);
        if (lane == 0) svec[r] = fmaxf(v + bm1[r], 0.f);
    }

    const float4* sm4 = (const float4*)sm;
    float4 m0 = sm4[lane], m1 = sm4[lane + 32];
#pragma unroll 4
    for (int k = 0; k < 32; ++k) {
        int r = w * 32 + k;
        const float4* wr = (const float4*)(W2 + (size_t)r * HID);
        float4 w0 = wr[lane], w1 = wr[lane + 32];
        float v = w0.x * m0.x + w0.y * m0.y + w0.z * m0.z + w0.w * m0.w
                + w1.x * m1.x + w1.y * m1.y + w1.z * m1.z + w1.w * m1.w;
#pragma unroll
        for (int o = 16; o > 0; o >>= 1) v += __shfl_xor_sync(0xffffffffu, v, o);
        if (lane == 0) smid[r] = v + b2[r];
    }
    __syncthreads();

    const float4* sd4 = (const float4*)smid;
    float4 d0 = sd4[lane], d1 = sd4[lane + 32];
#pragma unroll 4
    for (int k = 0; k < 32; ++k) {
        int r = w * 32 + k;
        const float4* wr = (const float4*)(Wfc + (size_t)r * HID);
        float4 w0 = wr[lane], w1 = wr[lane + 32];
        float v = w0.x * d0.x + w0.y * d0.y + w0.z * d0.z + w0.w * d0.w
                + w1.x * d1.x + w1.y * d1.y + w1.z * d1.z + w1.w * d1.w;
#pragma unroll
        for (int o = 16; o > 0; o >>= 1) v += __shfl_xor_sync(0xffffffffu, v, o);
        if (lane == 0) svec[MLPH + r] = v + bfc[r];
    }

    if (t < OUTD) {
        float avg = 0.f;
#pragma unroll
        for (int c = 0; c < SEGS; ++c) avg += g_speedp[b * SEGS + c];
        avg *= (1.0f / 1024.0f);
        float mx = fmaxf(fmaxf(g_maxp[b * 4], g_maxp[b * 4 + 1]),
                         fmaxf(g_maxp[b * 4 + 2], g_maxp[b * 4 + 3]));
        float den = rsqrtf(mx);
        svec[MLPH + HID + t] =
            fmaxf(fmaf(Wg[t * 2], avg, fmaf(Wg[t * 2 + 1], den, bg[t])), 0.f);
    }
    __syncthreads();

    if (w < OUTD) {
        const float* wp = Wp + (size_t)w * CAT;
        float o = 0.f;
#pragma unroll
        for (int j = lane; j < CAT; j += 32) o = fmaf(wp[j], svec[j], o);
#pragma unroll
        for (int s = 16; s > 0; s >>= 1) o += __shfl_xor_sync(0xffffffffu, o, s);
        if (lane == 0) out[b * OUTD + w] = o + bp[w];
    }
}

extern "C" void kernel_launch(void* const* d_in, const int* in_sizes, int n_in,
                              void* d_out, int out_size) {
    const float* x   = (const float*)d_in[0];
    const float* W1  = (const float*)d_in[1];
    const float* b1  = (const float*)d_in[2];
    const float* W2  = (const float*)d_in[3];
    const float* b2  = (const float*)d_in[4];
    const float* Wfc = (const float*)d_in[5];
    const float* bfc = (const float*)d_in[6];
    const float* Wg  = (const float*)d_in[7];
    const float* bg  = (const float*)d_in[8];
    const float* Wm0 = (const float*)d_in[9];
    const float* bm0 = (const float*)d_in[10];
    const float* Wm1 = (const float*)d_in[11];
    const float* bm1 = (const float*)d_in[12];
    const float* Wp  = (const float*)d_in[13];
    const float* bp  = (const float*)d_in[14];
    float* out = (float*)d_out;

    kA<<<PBLK + KCH, 256>>>(x, Wm0);
    kB<<<512, 256>>>(W1, b1);
    k3_final<<<32, 256>>>(W2, b2, Wfc, bfc, Wg, bg, Wm1, bm1, bm0, Wp, bp, out);
}